// round 3
// baseline (speedup 1.0000x reference)
#include <cuda_runtime.h>
#include <cstring>

#define B_SZ   1024
#define S_SZ   2048
#define F_SZ   9
#define NO_SZ  8
#define D_SZ   11
#define LB_SZ  3
#define T_STEPS 2044   // S - 1 - LB
#define LN_EPS 1e-3f

// ---------------------------------------------------------------------------
// Packed fp32x2 FMA (Blackwell FFMA2) — only reachable via PTX fma.rn.f32x2
// ---------------------------------------------------------------------------
__device__ __forceinline__ float2 ffma2(float2 a, float2 b, float2 c) {
    unsigned long long ra, rb, rc, rd;
    memcpy(&ra, &a, 8); memcpy(&rb, &b, 8); memcpy(&rc, &c, 8);
    asm("fma.rn.f32x2 %0, %1, %2, %3;" : "=l"(rd) : "l"(ra), "l"(rb), "l"(rc));
    float2 d; memcpy(&d, &rd, 8);
    return d;
}

// ---------------------------------------------------------------------------
// Per-CTA tile GEMM: C[N][8] = act( A[K][8] @ W[K][N] + bias[N] )
//   A in SMEM, k-major with 8 batch rows fastest (row-pair packed via f32x2)
//   W in GMEM row-major (N fastest -> coalesced LDG)
//   COLS = columns per thread (2 for N=512 with 256 threads, 1 for N=256)
// ---------------------------------------------------------------------------
template<int K, int COLS, bool TANH>
__device__ __forceinline__ void gemm8(const float* __restrict__ A,
                                      const float* __restrict__ W, int N,
                                      const float* __restrict__ bias,
                                      float* __restrict__ C)
{
    const int tid = threadIdx.x;
    const int n0 = (COLS == 2) ? (tid << 1) : tid;

    float2 acc[COLS][4];
#pragma unroll
    for (int c = 0; c < COLS; ++c) {
        float bv = bias[n0 + c];
#pragma unroll
        for (int p = 0; p < 4; ++p) acc[c][p] = make_float2(bv, bv);
    }

#pragma unroll 8
    for (int k = 0; k < K; ++k) {
        float wv0, wv1 = 0.f;
        if (COLS == 2) {
            float2 wp = *reinterpret_cast<const float2*>(W + (size_t)k * N + n0);
            wv0 = wp.x; wv1 = wp.y;
        } else {
            wv0 = W[(size_t)k * N + n0];
        }
        // broadcast loads of the 8-row activation slice (LDS.128 x2)
        float4 aA = *reinterpret_cast<const float4*>(A + k * 8);
        float4 aB = *reinterpret_cast<const float4*>(A + k * 8 + 4);
        float2 ap[4] = { make_float2(aA.x, aA.y), make_float2(aA.z, aA.w),
                         make_float2(aB.x, aB.y), make_float2(aB.z, aB.w) };
        float2 w20 = make_float2(wv0, wv0);
#pragma unroll
        for (int p = 0; p < 4; ++p) acc[0][p] = ffma2(ap[p], w20, acc[0][p]);
        if constexpr (COLS == 2) {
            float2 w21 = make_float2(wv1, wv1);
#pragma unroll
            for (int p = 0; p < 4; ++p) acc[1][p] = ffma2(ap[p], w21, acc[1][p]);
        }
    }

#pragma unroll
    for (int c = 0; c < COLS; ++c) {
#pragma unroll
        for (int p = 0; p < 4; ++p) {
            float2 v = acc[c][p];
            if (TANH) { v.x = tanhf(v.x); v.y = tanhf(v.y); }
            *reinterpret_cast<float2*>(C + (n0 + c) * 8 + 2 * p) = v;
        }
    }
}

// ---------------------------------------------------------------------------
// Persistent kernel: 128 CTAs x 8 batch rows, full 2044-step recurrence local.
// ---------------------------------------------------------------------------
__global__ __launch_bounds__(256)
void solver_kernel(const float* __restrict__ in0,
                   const float* __restrict__ g1,  const float* __restrict__ be1,
                   const float* __restrict__ w1,  const float* __restrict__ b1,
                   const float* __restrict__ w2,  const float* __restrict__ b2,
                   const float* __restrict__ wu,  const float* __restrict__ bu,
                   const float* __restrict__ g2,  const float* __restrict__ be2,
                   const float* __restrict__ wbeta,
                   const float* __restrict__ wd1, const float* __restrict__ bd1,
                   const float* __restrict__ wd2, const float* __restrict__ bd2,
                   const int*   __restrict__ fix, int nfix,
                   float* __restrict__ out)
{
    __shared__ float x33[33 * 8];      // LN'd encoder input (also dec2 scratch)
    __shared__ float buf512[512 * 8];  // h1 (enc1 out) / t (dec1 out) — disjoint lifetimes
    __shared__ float hbuf[256 * 8];    // enc2 out
    __shared__ float ubuf[256 * 8];    // upd out (pre-LN)
    __shared__ float comb[257 * 8];    // [LN2(u), ect]
    __shared__ float win[3 * 8 * 8];   // window ring: [phys][n][m]
    __shared__ float ybuf[8 * 8 * 16]; // 16-step output staging

    const int tid  = threadIdx.x;
    const int wid  = tid >> 5, lane = tid & 31;
    const int b_base = blockIdx.x * 8;

    const int f0 = (nfix > 0) ? fix[0] : -1;
    const int f1 = (nfix > 1) ? fix[1] : -1;

    // init window = initial[:, 0:3, :] = inputs[:, 0:3, 1:9]
    for (int idx = tid; idx < 192; idx += 256) {
        int j = idx / 64, rem = idx % 64, n = rem >> 3, m = rem & 7;
        win[j * 64 + n * 8 + m] = in0[((size_t)(b_base + m) * S_SZ + j) * F_SZ + 1 + n];
    }
    __syncthreads();

    for (int step = 0; step < T_STEPS; ++step) {
        const int i = step + LB_SZ;
        const int r = step % 3;   // logical j -> phys (r+j)%3 ; new y -> slot r

        // ---- stage 1: build x (lc|win), LN1, store k-major into x33 ----
        // NOTE: ln1_gamma/beta have shape (11,) and broadcast over the LAST
        // axis of (B, 3, 11) — index is the within-row channel (lane), NOT
        // the flattened j*11+lane.
        {
            const int m = wid;  // 8 warps, one batch row each
            for (int j = 0; j < 3; ++j) {
                int t = i - 3 + j;
                float v = 0.f;
                if (lane < 11) {
                    if (lane < 3) {
                        size_t base = ((size_t)(b_base + m) * S_SZ + t) * F_SZ;
                        float L = in0[base];
                        if (lane < 2) v = L;                       // loading, cumsum(==loading)
                        else v = (t > 0) ? (L - in0[base - F_SZ]) : 0.f;  // diff (padded)
                    } else {
                        v = win[((r + j) % 3) * 64 + (lane - 3) * 8 + m];
                    }
                }
                float s = v, s2 = v * v;
#pragma unroll
                for (int off = 16; off > 0; off >>= 1) {
                    s  += __shfl_xor_sync(0xffffffffu, s,  off);
                    s2 += __shfl_xor_sync(0xffffffffu, s2, off);
                }
                float mean = s * (1.f / 11.f);
                float var  = s2 * (1.f / 11.f) - mean * mean;
                float rs   = rsqrtf(var + LN_EPS);
                if (lane < 11) {
                    x33[(j * 11 + lane) * 8 + m] =
                        (v - mean) * rs * g1[lane] + be1[lane];
                }
            }
        }
        __syncthreads();

        gemm8<33, 2, true >(x33,    w1, 512, b1, buf512);  // h1 = tanh(x@enc_w1+b1)
        __syncthreads();
        gemm8<512, 1, false>(buf512, w2, 256, b2, hbuf);   // h  = h1@enc_w2+b2
        __syncthreads();
        gemm8<256, 1, false>(hbuf,   wu, 256, bu, ubuf);   // u  = h@upd_w+upd_b
        __syncthreads();

        // ---- stage 5: LN2(u) and ect = h@beta_w -> comb[257] ----
        {
            const int m = wid;
            float uv[8];
            float su = 0.f, sq = 0.f, se = 0.f;
#pragma unroll
            for (int q = 0; q < 8; ++q) {
                int n = lane + 32 * q;
                float x = ubuf[n * 8 + m];
                uv[q] = x; su += x; sq += x * x;
                se += hbuf[n * 8 + m] * wbeta[n];
            }
#pragma unroll
            for (int off = 16; off > 0; off >>= 1) {
                su += __shfl_xor_sync(0xffffffffu, su, off);
                sq += __shfl_xor_sync(0xffffffffu, sq, off);
                se += __shfl_xor_sync(0xffffffffu, se, off);
            }
            float mean = su * (1.f / 256.f);
            float var  = sq * (1.f / 256.f) - mean * mean;
            float rs   = rsqrtf(var + LN_EPS);
#pragma unroll
            for (int q = 0; q < 8; ++q) {
                int n = lane + 32 * q;
                comb[n * 8 + m] = (uv[q] - mean) * rs * g2[n] + be2[n];
            }
            if (lane == 0) comb[256 * 8 + m] = se;
        }
        __syncthreads();

        gemm8<257, 2, true>(comb, wd1, 512, bd1, buf512);  // t = tanh(comb@dec_w1+bd1)
        __syncthreads();

        // ---- stage 7: y = t@dec_w2+bd2 (k-split x4), fix, window, staging ----
        {
            const int ks = tid >> 6;          // k-quarter 0..3
            const int nm = tid & 63;
            const int n = nm & 7, m = nm >> 3;
            const int k0 = ks * 128;
            float a0 = 0.f, a1 = 0.f, a2 = 0.f, a3 = 0.f;
#pragma unroll 8
            for (int k = 0; k < 128; k += 4) {
                a0 += buf512[(k0 + k)     * 8 + m] * wd2[(k0 + k)     * 8 + n];
                a1 += buf512[(k0 + k + 1) * 8 + m] * wd2[(k0 + k + 1) * 8 + n];
                a2 += buf512[(k0 + k + 2) * 8 + m] * wd2[(k0 + k + 2) * 8 + n];
                a3 += buf512[(k0 + k + 3) * 8 + m] * wd2[(k0 + k + 3) * 8 + n];
            }
            x33[tid] = (a0 + a1) + (a2 + a3);   // x33 reused as scratch (dead here)
        }
        __syncthreads();
        if (tid < 64) {
            const int n = tid & 7, m = tid >> 3;
            float acc = x33[tid] + x33[64 + tid] + x33[128 + tid] + x33[192 + tid] + bd2[n];
            if (n == f0 || n == f1)
                acc = in0[((size_t)(b_base + m) * S_SZ + (i + 1)) * F_SZ + 1 + n];
            ybuf[(n * 8 + m) * 16 + (step & 15)] = acc;
            win[r * 64 + n * 8 + m] = acc;      // append y into ring (slot of old oldest)
        }
        __syncthreads();

        if ((step & 15) == 15 && tid < 64) {
            const int n = tid >> 3, m = tid & 7;
            const float4* src = reinterpret_cast<const float4*>(&ybuf[(n * 8 + m) * 16]);
            float4* dst = reinterpret_cast<float4*>(
                &out[(size_t)n * B_SZ * T_STEPS + (size_t)(b_base + m) * T_STEPS + (step - 15)]);
            dst[0] = src[0]; dst[1] = src[1]; dst[2] = src[2]; dst[3] = src[3];
        }
    }

    // tail flush (T_STEPS % 16 == 12): steps 2032..2043 live in ybuf slots 0..11
    if (tid < 64) {
        const int n = tid >> 3, m = tid & 7;
        const int step0 = (T_STEPS / 16) * 16;
        for (int s2 = 0; s2 < T_STEPS - step0; ++s2)
            out[(size_t)n * B_SZ * T_STEPS + (size_t)(b_base + m) * T_STEPS + step0 + s2]
                = ybuf[(n * 8 + m) * 16 + s2];
    }
}

extern "C" void kernel_launch(void* const* d_in, const int* in_sizes, int n_in,
                              void* d_out, int out_size) {
    const float* in0   = (const float*)d_in[0];
    const float* g1    = (const float*)d_in[1];
    const float* be1   = (const float*)d_in[2];
    const float* w1    = (const float*)d_in[3];
    const float* b1    = (const float*)d_in[4];
    const float* w2    = (const float*)d_in[5];
    const float* b2    = (const float*)d_in[6];
    const float* wu    = (const float*)d_in[7];
    const float* bu    = (const float*)d_in[8];
    const float* g2    = (const float*)d_in[9];
    const float* be2   = (const float*)d_in[10];
    const float* wbeta = (const float*)d_in[11];
    const float* wd1   = (const float*)d_in[12];
    const float* bd1   = (const float*)d_in[13];
    const float* wd2   = (const float*)d_in[14];
    const float* bd2   = (const float*)d_in[15];
    const int*   fix   = (const int*)d_in[16];
    const int    nfix  = in_sizes[16];

    solver_kernel<<<B_SZ / 8, 256>>>(in0, g1, be1, w1, b1, w2, b2, wu, bu,
                                     g2, be2, wbeta, wd1, bd1, wd2, bd2,
                                     fix, nfix, (float*)d_out);
}

// round 4
// speedup vs baseline: 1.0252x; 1.0252x over previous
#include <cuda_runtime.h>
#include <cstring>

#define B_SZ   1024
#define S_SZ   2048
#define F_SZ   9
#define LB_SZ  3
#define T_STEPS 2044   // S - 1 - LB
#define LN_EPS 1e-3f
#define NTHR   512

// ---------------------------------------------------------------------------
// Packed fp32x2 FMA (Blackwell FFMA2) — only reachable via PTX fma.rn.f32x2
// ---------------------------------------------------------------------------
__device__ __forceinline__ float2 ffma2(float2 a, float2 b, float2 c) {
    unsigned long long ra, rb, rc, rd;
    memcpy(&ra, &a, 8); memcpy(&rb, &b, 8); memcpy(&rc, &c, 8);
    asm("fma.rn.f32x2 %0, %1, %2, %3;" : "=l"(rd) : "l"(ra), "l"(rb), "l"(rc));
    float2 d; memcpy(&d, &rd, 8);
    return d;
}

// ---------------------------------------------------------------------------
// N=512 GEMM, 512 threads: 2 row-groups (4 rows) x 256 col-threads x 2 cols.
// C[N][8] = act(A[K][8] @ W[K][512] + bias), A k-major SMEM, W gmem row-major.
// Per k: LDS.128 (4 rows, warp-broadcast) + LDG.64 (2 cols) + 4 FFMA2.
// ---------------------------------------------------------------------------
template<int K, bool TANH>
__device__ __forceinline__ void gemm_n512(const float* __restrict__ A,
                                          const float* __restrict__ W,
                                          const float* __restrict__ bias,
                                          float* __restrict__ C)
{
    const int tid = threadIdx.x;
    const int g   = tid >> 8;           // row group: rows 4g..4g+3
    const int n0  = (tid & 255) << 1;   // 2 columns
    const float b0 = bias[n0], b1 = bias[n0 + 1];
    float2 a00 = make_float2(b0, b0), a01 = make_float2(b0, b0);
    float2 a10 = make_float2(b1, b1), a11 = make_float2(b1, b1);

#pragma unroll 8
    for (int k = 0; k < K; ++k) {
        float2 wp = *reinterpret_cast<const float2*>(W + (size_t)k * 512 + n0);
        float4 av = *reinterpret_cast<const float4*>(A + k * 8 + 4 * g);
        float2 apA = make_float2(av.x, av.y), apB = make_float2(av.z, av.w);
        float2 w0 = make_float2(wp.x, wp.x), w1 = make_float2(wp.y, wp.y);
        a00 = ffma2(apA, w0, a00); a01 = ffma2(apB, w0, a01);
        a10 = ffma2(apA, w1, a10); a11 = ffma2(apB, w1, a11);
    }
    if (TANH) {
        a00.x = tanhf(a00.x); a00.y = tanhf(a00.y);
        a01.x = tanhf(a01.x); a01.y = tanhf(a01.y);
        a10.x = tanhf(a10.x); a10.y = tanhf(a10.y);
        a11.x = tanhf(a11.x); a11.y = tanhf(a11.y);
    }
    *reinterpret_cast<float2*>(C + n0 * 8 + 4 * g)           = a00;
    *reinterpret_cast<float2*>(C + n0 * 8 + 4 * g + 2)       = a01;
    *reinterpret_cast<float2*>(C + (n0 + 1) * 8 + 4 * g)     = a10;
    *reinterpret_cast<float2*>(C + (n0 + 1) * 8 + 4 * g + 2) = a11;
}

// ---------------------------------------------------------------------------
// N=256 GEMM partial, 2-way k-split: half = tid>>8 covers k in
// [half*K/2, (half+1)*K/2), thread owns 1 column, all 8 rows.
// Partial (no bias) written to part[n*8 + m].
// ---------------------------------------------------------------------------
template<int KTOT>
__device__ __forceinline__ void gemm_n256_part(const float* __restrict__ A,
                                               const float* __restrict__ W,
                                               float* __restrict__ p0,
                                               float* __restrict__ p1)
{
    const int tid  = threadIdx.x;
    const int half = tid >> 8;
    const int n    = tid & 255;
    const int k0   = half * (KTOT / 2);
    float* part = half ? p1 : p0;

    float2 acc[4];
#pragma unroll
    for (int p = 0; p < 4; ++p) acc[p] = make_float2(0.f, 0.f);

#pragma unroll 8
    for (int k = 0; k < KTOT / 2; ++k) {
        float wv = W[(size_t)(k0 + k) * 256 + n];
        float4 aA = *reinterpret_cast<const float4*>(A + (k0 + k) * 8);
        float4 aB = *reinterpret_cast<const float4*>(A + (k0 + k) * 8 + 4);
        float2 w2 = make_float2(wv, wv);
        acc[0] = ffma2(make_float2(aA.x, aA.y), w2, acc[0]);
        acc[1] = ffma2(make_float2(aA.z, aA.w), w2, acc[1]);
        acc[2] = ffma2(make_float2(aB.x, aB.y), w2, acc[2]);
        acc[3] = ffma2(make_float2(aB.z, aB.w), w2, acc[3]);
    }
#pragma unroll
    for (int p = 0; p < 4; ++p)
        *reinterpret_cast<float2*>(part + n * 8 + 2 * p) = acc[p];
}

// Combine two 2048-float partials + bias into C (all 512 threads, float4).
__device__ __forceinline__ void combine256(const float* __restrict__ p0,
                                           const float* __restrict__ p1,
                                           const float* __restrict__ bias,
                                           float* __restrict__ C)
{
    const int tid = threadIdx.x;
    float4 a = reinterpret_cast<const float4*>(p0)[tid];
    float4 b = reinterpret_cast<const float4*>(p1)[tid];
    float bv = bias[tid >> 1];
    float4 r = make_float4(a.x + b.x + bv, a.y + b.y + bv,
                           a.z + b.z + bv, a.w + b.w + bv);
    reinterpret_cast<float4*>(C)[tid] = r;
}

// ---------------------------------------------------------------------------
// Persistent kernel: 128 CTAs x 8 batch rows x 512 threads.
// ---------------------------------------------------------------------------
__global__ __launch_bounds__(NTHR)
void solver_kernel(const float* __restrict__ in0,
                   const float* __restrict__ g1,  const float* __restrict__ be1,
                   const float* __restrict__ w1,  const float* __restrict__ b1,
                   const float* __restrict__ w2,  const float* __restrict__ b2,
                   const float* __restrict__ wu,  const float* __restrict__ bu,
                   const float* __restrict__ g2,  const float* __restrict__ be2,
                   const float* __restrict__ wbeta,
                   const float* __restrict__ wd1, const float* __restrict__ bd1,
                   const float* __restrict__ wd2, const float* __restrict__ bd2,
                   const int*   __restrict__ fix, int nfix,
                   float* __restrict__ out)
{
    __shared__ __align__(16) float x33[33 * 8];      // LN'd encoder input
    __shared__ __align__(16) float buf512[512 * 8];  // h1 / t / g3-partial1
    __shared__ __align__(16) float hbuf[256 * 8];    // h (enc2 out) / g5 partials
    __shared__ __align__(16) float ubuf[256 * 8];    // u (upd out) / g2-partial0
    __shared__ __align__(16) float comb[257 * 8];    // [LN2(u), ect] / g2-p1 / g3-p0
    __shared__ __align__(16) float win[3 * 8 * 8];   // window ring [phys][n][m]
    __shared__ __align__(16) float ybuf[8 * 8 * 16]; // 16-step output staging

    const int tid  = threadIdx.x;
    const int wid  = tid >> 5, lane = tid & 31;
    const int b_base = blockIdx.x * 8;

    const int f0 = (nfix > 0) ? fix[0] : -1;
    const int f1 = (nfix > 1) ? fix[1] : -1;

    // init window = inputs[:, 0:3, 1:9]
    for (int idx = tid; idx < 192; idx += NTHR) {
        int j = idx / 64, rem = idx % 64, n = rem >> 3, m = rem & 7;
        win[j * 64 + n * 8 + m] = in0[((size_t)(b_base + m) * S_SZ + j) * F_SZ + 1 + n];
    }
    __syncthreads();

    for (int step = 0; step < T_STEPS; ++step) {
        const int i = step + LB_SZ;
        const int r = step % 3;

        // ---- LN1: gamma/beta broadcast over LAST axis (index = lane) ----
        if (wid < 8) {
            const int m = wid;
            for (int j = 0; j < 3; ++j) {
                int t = i - 3 + j;
                float v = 0.f;
                if (lane < 11) {
                    if (lane < 3) {
                        size_t base = ((size_t)(b_base + m) * S_SZ + t) * F_SZ;
                        float L = in0[base];
                        if (lane < 2) v = L;                      // loading, cumsum
                        else v = (t > 0) ? (L - in0[base - F_SZ]) : 0.f;
                    } else {
                        v = win[((r + j) % 3) * 64 + (lane - 3) * 8 + m];
                    }
                }
                float s = v, s2 = v * v;
#pragma unroll
                for (int off = 16; off > 0; off >>= 1) {
                    s  += __shfl_xor_sync(0xffffffffu, s,  off);
                    s2 += __shfl_xor_sync(0xffffffffu, s2, off);
                }
                float mean = s * (1.f / 11.f);
                float var  = s2 * (1.f / 11.f) - mean * mean;
                float rs   = rsqrtf(var + LN_EPS);
                if (lane < 11)
                    x33[(j * 11 + lane) * 8 + m] = (v - mean) * rs * g1[lane] + be1[lane];
            }
        }
        __syncthreads();

        gemm_n512<33, true>(x33, w1, b1, buf512);          // h1 = tanh(x@w1+b1)
        __syncthreads();

        gemm_n256_part<512>(buf512, w2, ubuf, comb);       // h partials
        __syncthreads();
        combine256(ubuf, comb, b2, hbuf);                  // h
        __syncthreads();

        gemm_n256_part<256>(hbuf, wu, comb, buf512);       // u partials
        __syncthreads();
        combine256(comb, buf512, bu, ubuf);                // u
        __syncthreads();

        // ---- LN2(u) + ect = h@beta_w -> comb[257][8] ----
        if (wid < 8) {
            const int m = wid;
            float uv[8];
            float su = 0.f, sq = 0.f, se = 0.f;
#pragma unroll
            for (int q = 0; q < 8; ++q) {
                int n = lane + 32 * q;
                float x = ubuf[n * 8 + m];
                uv[q] = x; su += x; sq += x * x;
                se += hbuf[n * 8 + m] * wbeta[n];
            }
#pragma unroll
            for (int off = 16; off > 0; off >>= 1) {
                su += __shfl_xor_sync(0xffffffffu, su, off);
                sq += __shfl_xor_sync(0xffffffffu, sq, off);
                se += __shfl_xor_sync(0xffffffffu, se, off);
            }
            float mean = su * (1.f / 256.f);
            float var  = sq * (1.f / 256.f) - mean * mean;
            float rs   = rsqrtf(var + LN_EPS);
#pragma unroll
            for (int q = 0; q < 8; ++q) {
                int n = lane + 32 * q;
                comb[n * 8 + m] = (uv[q] - mean) * rs * g2[n] + be2[n];
            }
            if (lane == 0) comb[256 * 8 + m] = se;
        }
        __syncthreads();

        gemm_n512<257, true>(comb, wd1, bd1, buf512);      // t = tanh(comb@wd1+bd1)
        __syncthreads();

        // ---- y = t@wd2 + bd2 : 8-way k-split, partials in hbuf ----
        {
            const int ks = tid >> 6, nm = tid & 63;
            const int n = nm & 7, m = nm >> 3, k0 = ks * 64;
            float a0 = 0.f, a1 = 0.f;
#pragma unroll 8
            for (int k = 0; k < 64; k += 2) {
                a0 += buf512[(k0 + k)     * 8 + m] * wd2[(k0 + k)     * 8 + n];
                a1 += buf512[(k0 + k + 1) * 8 + m] * wd2[(k0 + k + 1) * 8 + n];
            }
            hbuf[ks * 64 + nm] = a0 + a1;
        }
        __syncthreads();
        if (tid < 64) {
            const int n = tid & 7, m = tid >> 3;
            float acc = bd2[n];
#pragma unroll
            for (int ks = 0; ks < 8; ++ks) acc += hbuf[ks * 64 + tid];
            if (n == f0 || n == f1)
                acc = in0[((size_t)(b_base + m) * S_SZ + (i + 1)) * F_SZ + 1 + n];
            ybuf[(n * 8 + m) * 16 + (step & 15)] = acc;
            win[r * 64 + n * 8 + m] = acc;
        }
        __syncthreads();

        if ((step & 15) == 15 && tid < 64) {
            const int n = tid >> 3, m = tid & 7;
            const float4* src = reinterpret_cast<const float4*>(&ybuf[(n * 8 + m) * 16]);
            float4* dst = reinterpret_cast<float4*>(
                &out[(size_t)n * B_SZ * T_STEPS + (size_t)(b_base + m) * T_STEPS + (step - 15)]);
            dst[0] = src[0]; dst[1] = src[1]; dst[2] = src[2]; dst[3] = src[3];
        }
    }

    // tail flush (T_STEPS % 16 == 12)
    if (tid < 64) {
        const int n = tid >> 3, m = tid & 7;
        const int step0 = (T_STEPS / 16) * 16;
        for (int s2 = 0; s2 < T_STEPS - step0; ++s2)
            out[(size_t)n * B_SZ * T_STEPS + (size_t)(b_base + m) * T_STEPS + step0 + s2]
                = ybuf[(n * 8 + m) * 16 + s2];
    }
}

extern "C" void kernel_launch(void* const* d_in, const int* in_sizes, int n_in,
                              void* d_out, int out_size) {
    const float* in0   = (const float*)d_in[0];
    const float* g1    = (const float*)d_in[1];
    const float* be1   = (const float*)d_in[2];
    const float* w1    = (const float*)d_in[3];
    const float* b1    = (const float*)d_in[4];
    const float* w2    = (const float*)d_in[5];
    const float* b2    = (const float*)d_in[6];
    const float* wu    = (const float*)d_in[7];
    const float* bu    = (const float*)d_in[8];
    const float* g2    = (const float*)d_in[9];
    const float* be2   = (const float*)d_in[10];
    const float* wbeta = (const float*)d_in[11];
    const float* wd1   = (const float*)d_in[12];
    const float* bd1   = (const float*)d_in[13];
    const float* wd2   = (const float*)d_in[14];
    const float* bd2   = (const float*)d_in[15];
    const int*   fix   = (const int*)d_in[16];
    const int    nfix  = in_sizes[16];

    solver_kernel<<<B_SZ / 8, NTHR>>>(in0, g1, be1, w1, b1, w2, b2, wu, bu,
                                      g2, be2, wbeta, wd1, bd1, wd2, bd2,
                                      fix, nfix, (float*)d_out);
}

// round 6
// speedup vs baseline: 1.3970x; 1.3626x over previous
#include <cuda_runtime.h>
#include <cstring>

#define B_SZ   1024
#define S_SZ   2048
#define F_SZ   9
#define LB_SZ  3
#define T_STEPS 2044   // S - 1 - LB
#define LN_EPS 1e-3f
#define NTHR   512

// ---------------------------------------------------------------------------
// Packed fp32x2 FMA (Blackwell FFMA2) — only reachable via PTX fma.rn.f32x2
// ---------------------------------------------------------------------------
__device__ __forceinline__ float2 ffma2(float2 a, float2 b, float2 c) {
    unsigned long long ra, rb, rc, rd;
    memcpy(&ra, &a, 8); memcpy(&rb, &b, 8); memcpy(&rc, &c, 8);
    asm("fma.rn.f32x2 %0, %1, %2, %3;" : "=l"(rd) : "l"(ra), "l"(rb), "l"(rc));
    float2 d; memcpy(&d, &rd, 8);
    return d;
}

// ---------------------------------------------------------------------------
// N=512 GEMM, 512 threads: 2 row-groups (4 rows) x 256 col-threads x 2 cols.
// Weight loads are software-pipelined: batch kb+1's 8 LDG.64 issue before
// batch kb's FFMA2s consume wreg — guarantees MLP=8 per warp.
// ---------------------------------------------------------------------------
template<int K, bool TANH>
__device__ __forceinline__ void gemm_n512(const float* __restrict__ A,
                                          const float* __restrict__ W,
                                          const float* __restrict__ bias,
                                          float* __restrict__ C)
{
    const int tid = threadIdx.x;
    const int g   = tid >> 8;           // row group: rows 4g..4g+3
    const int n0  = (tid & 255) << 1;   // 2 columns
    const float* Wp = W + n0;
    const float b0 = bias[n0], b1 = bias[n0 + 1];
    float2 a00 = make_float2(b0, b0), a01 = make_float2(b0, b0);
    float2 a10 = make_float2(b1, b1), a11 = make_float2(b1, b1);

    constexpr int UB = 8;
    constexpr int NB = K / UB;          // full batches

    float2 wreg[UB];
#pragma unroll
    for (int u = 0; u < UB; ++u)
        wreg[u] = *reinterpret_cast<const float2*>(Wp + (size_t)u * 512);

    for (int kb = 0; kb < NB - 1; ++kb) {
        float2 wnxt[UB];
        const float* Wn = Wp + (size_t)(kb + 1) * UB * 512;
#pragma unroll
        for (int u = 0; u < UB; ++u)
            wnxt[u] = *reinterpret_cast<const float2*>(Wn + (size_t)u * 512);
#pragma unroll
        for (int u = 0; u < UB; ++u) {
            const int k = kb * UB + u;
            float4 av = *reinterpret_cast<const float4*>(A + k * 8 + 4 * g);
            float2 apA = make_float2(av.x, av.y), apB = make_float2(av.z, av.w);
            float2 w0 = make_float2(wreg[u].x, wreg[u].x);
            float2 w1 = make_float2(wreg[u].y, wreg[u].y);
            a00 = ffma2(apA, w0, a00); a01 = ffma2(apB, w0, a01);
            a10 = ffma2(apA, w1, a10); a11 = ffma2(apB, w1, a11);
        }
#pragma unroll
        for (int u = 0; u < UB; ++u) wreg[u] = wnxt[u];
    }
    // last full batch (no prefetch)
#pragma unroll
    for (int u = 0; u < UB; ++u) {
        const int k = (NB - 1) * UB + u;
        float4 av = *reinterpret_cast<const float4*>(A + k * 8 + 4 * g);
        float2 apA = make_float2(av.x, av.y), apB = make_float2(av.z, av.w);
        float2 w0 = make_float2(wreg[u].x, wreg[u].x);
        float2 w1 = make_float2(wreg[u].y, wreg[u].y);
        a00 = ffma2(apA, w0, a00); a01 = ffma2(apB, w0, a01);
        a10 = ffma2(apA, w1, a10); a11 = ffma2(apB, w1, a11);
    }
    // remainder K % UB
#pragma unroll
    for (int k = NB * UB; k < K; ++k) {
        float2 wp = *reinterpret_cast<const float2*>(Wp + (size_t)k * 512);
        float4 av = *reinterpret_cast<const float4*>(A + k * 8 + 4 * g);
        float2 apA = make_float2(av.x, av.y), apB = make_float2(av.z, av.w);
        float2 w0 = make_float2(wp.x, wp.x), w1 = make_float2(wp.y, wp.y);
        a00 = ffma2(apA, w0, a00); a01 = ffma2(apB, w0, a01);
        a10 = ffma2(apA, w1, a10); a11 = ffma2(apB, w1, a11);
    }

    if (TANH) {
        a00.x = tanhf(a00.x); a00.y = tanhf(a00.y);
        a01.x = tanhf(a01.x); a01.y = tanhf(a01.y);
        a10.x = tanhf(a10.x); a10.y = tanhf(a10.y);
        a11.x = tanhf(a11.x); a11.y = tanhf(a11.y);
    }
    *reinterpret_cast<float2*>(C + n0 * 8 + 4 * g)           = a00;
    *reinterpret_cast<float2*>(C + n0 * 8 + 4 * g + 2)       = a01;
    *reinterpret_cast<float2*>(C + (n0 + 1) * 8 + 4 * g)     = a10;
    *reinterpret_cast<float2*>(C + (n0 + 1) * 8 + 4 * g + 2) = a11;
}

// ---------------------------------------------------------------------------
// N=256 GEMM partial, 2-way k-split, same register prefetch pipeline.
// half = tid>>8 covers k in [half*K/2, ...), thread owns 1 column, 8 rows.
// ---------------------------------------------------------------------------
template<int KTOT>
__device__ __forceinline__ void gemm_n256_part(const float* __restrict__ A,
                                               const float* __restrict__ W,
                                               float* __restrict__ p0,
                                               float* __restrict__ p1)
{
    const int tid  = threadIdx.x;
    const int half = tid >> 8;
    const int n    = tid & 255;
    const int k0   = half * (KTOT / 2);
    const float* Wp = W + (size_t)k0 * 256 + n;
    const float* Ap = A + k0 * 8;
    float* part = half ? p1 : p0;

    float2 acc[4];
#pragma unroll
    for (int p = 0; p < 4; ++p) acc[p] = make_float2(0.f, 0.f);

    constexpr int KH = KTOT / 2;
    constexpr int UB = 8;
    constexpr int NB = KH / UB;     // exact for KH=256,128

    float wreg[UB];
#pragma unroll
    for (int u = 0; u < UB; ++u) wreg[u] = Wp[(size_t)u * 256];

    for (int kb = 0; kb < NB - 1; ++kb) {
        float wnxt[UB];
        const float* Wn = Wp + (size_t)(kb + 1) * UB * 256;
#pragma unroll
        for (int u = 0; u < UB; ++u) wnxt[u] = Wn[(size_t)u * 256];
#pragma unroll
        for (int u = 0; u < UB; ++u) {
            const int k = kb * UB + u;
            float4 aA = *reinterpret_cast<const float4*>(Ap + k * 8);
            float4 aB = *reinterpret_cast<const float4*>(Ap + k * 8 + 4);
            float2 w2 = make_float2(wreg[u], wreg[u]);
            acc[0] = ffma2(make_float2(aA.x, aA.y), w2, acc[0]);
            acc[1] = ffma2(make_float2(aA.z, aA.w), w2, acc[1]);
            acc[2] = ffma2(make_float2(aB.x, aB.y), w2, acc[2]);
            acc[3] = ffma2(make_float2(aB.z, aB.w), w2, acc[3]);
        }
#pragma unroll
        for (int u = 0; u < UB; ++u) wreg[u] = wnxt[u];
    }
#pragma unroll
    for (int u = 0; u < UB; ++u) {
        const int k = (NB - 1) * UB + u;
        float4 aA = *reinterpret_cast<const float4*>(Ap + k * 8);
        float4 aB = *reinterpret_cast<const float4*>(Ap + k * 8 + 4);
        float2 w2 = make_float2(wreg[u], wreg[u]);
        acc[0] = ffma2(make_float2(aA.x, aA.y), w2, acc[0]);
        acc[1] = ffma2(make_float2(aA.z, aA.w), w2, acc[1]);
        acc[2] = ffma2(make_float2(aB.x, aB.y), w2, acc[2]);
        acc[3] = ffma2(make_float2(aB.z, aB.w), w2, acc[3]);
    }

#pragma unroll
    for (int p = 0; p < 4; ++p)
        *reinterpret_cast<float2*>(part + n * 8 + 2 * p) = acc[p];
}

// Combine two 2048-float partials + bias into C (all 512 threads, float4).
__device__ __forceinline__ void combine256(const float* __restrict__ p0,
                                           const float* __restrict__ p1,
                                           const float* __restrict__ bias,
                                           float* __restrict__ C)
{
    const int tid = threadIdx.x;
    float4 a = reinterpret_cast<const float4*>(p0)[tid];
    float4 b = reinterpret_cast<const float4*>(p1)[tid];
    float bv = bias[tid >> 1];
    float4 r = make_float4(a.x + b.x + bv, a.y + b.y + bv,
                           a.z + b.z + bv, a.w + b.w + bv);
    reinterpret_cast<float4*>(C)[tid] = r;
}

// ---------------------------------------------------------------------------
// Persistent kernel: 128 CTAs x 8 batch rows x 512 threads.
// ---------------------------------------------------------------------------
__global__ __launch_bounds__(NTHR)
void solver_kernel(const float* __restrict__ in0,
                   const float* __restrict__ g1,  const float* __restrict__ be1,
                   const float* __restrict__ w1,  const float* __restrict__ b1,
                   const float* __restrict__ w2,  const float* __restrict__ b2,
                   const float* __restrict__ wu,  const float* __restrict__ bu,
                   const float* __restrict__ g2,  const float* __restrict__ be2,
                   const float* __restrict__ wbeta,
                   const float* __restrict__ wd1, const float* __restrict__ bd1,
                   const float* __restrict__ wd2, const float* __restrict__ bd2,
                   const int*   __restrict__ fix, int nfix,
                   float* __restrict__ out)
{
    __shared__ __align__(16) float x33[33 * 8];      // LN'd encoder input
    __shared__ __align__(16) float buf512[512 * 8];  // h1 / t / g3-partial1
    __shared__ __align__(16) float hbuf[256 * 8];    // h (enc2 out) / dec2 partials
    __shared__ __align__(16) float ubuf[256 * 8];    // u (upd out) / g2-partial0
    __shared__ __align__(16) float comb[257 * 8];    // [LN2(u), ect] / g2-p1 / g3-p0
    __shared__ __align__(16) float win[3 * 8 * 8];   // window ring [phys][n][m]
    __shared__ __align__(16) float ybuf[8 * 8 * 16]; // 16-step output staging

    const int tid  = threadIdx.x;
    const int wid  = tid >> 5, lane = tid & 31;
    const int b_base = blockIdx.x * 8;

    const int f0 = (nfix > 0) ? fix[0] : -1;
    const int f1 = (nfix > 1) ? fix[1] : -1;

    // init window = inputs[:, 0:3, 1:9]
    for (int idx = tid; idx < 192; idx += NTHR) {
        int j = idx / 64, rem = idx % 64, n = rem >> 3, m = rem & 7;
        win[j * 64 + n * 8 + m] = in0[((size_t)(b_base + m) * S_SZ + j) * F_SZ + 1 + n];
    }
    __syncthreads();

    for (int step = 0; step < T_STEPS; ++step) {
        const int i = step + LB_SZ;
        const int r = step % 3;

        // ---- LN1: gamma/beta broadcast over LAST axis (index = lane) ----
        if (wid < 8) {
            const int m = wid;
            for (int j = 0; j < 3; ++j) {
                int t = i - 3 + j;
                float v = 0.f;
                if (lane < 11) {
                    if (lane < 3) {
                        size_t base = ((size_t)(b_base + m) * S_SZ + t) * F_SZ;
                        float L = in0[base];
                        if (lane < 2) v = L;                      // loading, cumsum
                        else v = (t > 0) ? (L - in0[base - F_SZ]) : 0.f;
                    } else {
                        v = win[((r + j) % 3) * 64 + (lane - 3) * 8 + m];
                    }
                }
                float s = v, s2 = v * v;
#pragma unroll
                for (int off = 16; off > 0; off >>= 1) {
                    s  += __shfl_xor_sync(0xffffffffu, s,  off);
                    s2 += __shfl_xor_sync(0xffffffffu, s2, off);
                }
                float mean = s * (1.f / 11.f);
                float var  = s2 * (1.f / 11.f) - mean * mean;
                float rs   = rsqrtf(var + LN_EPS);
                if (lane < 11)
                    x33[(j * 11 + lane) * 8 + m] = (v - mean) * rs * g1[lane] + be1[lane];
            }
        }
        __syncthreads();

        gemm_n512<33, true>(x33, w1, b1, buf512);          // h1 = tanh(x@w1+b1)
        __syncthreads();

        gemm_n256_part<512>(buf512, w2, ubuf, comb);       // h partials
        __syncthreads();
        combine256(ubuf, comb, b2, hbuf);                  // h
        __syncthreads();

        gemm_n256_part<256>(hbuf, wu, comb, buf512);       // u partials
        __syncthreads();
        combine256(comb, buf512, bu, ubuf);                // u
        __syncthreads();

        // ---- LN2(u) + ect = h@beta_w -> comb[257][8] ----
        if (wid < 8) {
            const int m = wid;
            float uv[8];
            float su = 0.f, sq = 0.f, se = 0.f;
#pragma unroll
            for (int q = 0; q < 8; ++q) {
                int n = lane + 32 * q;
                float x = ubuf[n * 8 + m];
                uv[q] = x; su += x; sq += x * x;
                se += hbuf[n * 8 + m] * wbeta[n];
            }
#pragma unroll
            for (int off = 16; off > 0; off >>= 1) {
                su += __shfl_xor_sync(0xffffffffu, su, off);
                sq += __shfl_xor_sync(0xffffffffu, sq, off);
                se += __shfl_xor_sync(0xffffffffu, se, off);
            }
            float mean = su * (1.f / 256.f);
            float var  = sq * (1.f / 256.f) - mean * mean;
            float rs   = rsqrtf(var + LN_EPS);
#pragma unroll
            for (int q = 0; q < 8; ++q) {
                int n = lane + 32 * q;
                comb[n * 8 + m] = (uv[q] - mean) * rs * g2[n] + be2[n];
            }
            if (lane == 0) comb[256 * 8 + m] = se;
        }
        __syncthreads();

        gemm_n512<257, true>(comb, wd1, bd1, buf512);      // t = tanh(comb@wd1+bd1)
        __syncthreads();

        // ---- y = t@wd2 + bd2 : 8-way k-split, partials in hbuf ----
        {
            const int ks = tid >> 6, nm = tid & 63;
            const int n = nm & 7, m = nm >> 3, k0 = ks * 64;
            float a0 = 0.f, a1 = 0.f;
#pragma unroll 8
            for (int k = 0; k < 64; k += 2) {
                a0 += buf512[(k0 + k)     * 8 + m] * wd2[(k0 + k)     * 8 + n];
                a1 += buf512[(k0 + k + 1) * 8 + m] * wd2[(k0 + k + 1) * 8 + n];
            }
            hbuf[ks * 64 + nm] = a0 + a1;
        }
        __syncthreads();
        if (tid < 64) {
            const int n = tid & 7, m = tid >> 3;
            float acc = bd2[n];
#pragma unroll
            for (int ks = 0; ks < 8; ++ks) acc += hbuf[ks * 64 + tid];
            if (n == f0 || n == f1)
                acc = in0[((size_t)(b_base + m) * S_SZ + (i + 1)) * F_SZ + 1 + n];
            ybuf[(n * 8 + m) * 16 + (step & 15)] = acc;
            win[r * 64 + n * 8 + m] = acc;
        }
        __syncthreads();

        if ((step & 15) == 15 && tid < 64) {
            const int n = tid >> 3, m = tid & 7;
            const float4* src = reinterpret_cast<const float4*>(&ybuf[(n * 8 + m) * 16]);
            float4* dst = reinterpret_cast<float4*>(
                &out[(size_t)n * B_SZ * T_STEPS + (size_t)(b_base + m) * T_STEPS + (step - 15)]);
            dst[0] = src[0]; dst[1] = src[1]; dst[2] = src[2]; dst[3] = src[3];
        }
    }

    // tail flush (T_STEPS % 16 == 12)
    if (tid < 64) {
        const int n = tid >> 3, m = tid & 7;
        const int step0 = (T_STEPS / 16) * 16;
        for (int s2 = 0; s2 < T_STEPS - step0; ++s2)
            out[(size_t)n * B_SZ * T_STEPS + (size_t)(b_base + m) * T_STEPS + step0 + s2]
                = ybuf[(n * 8 + m) * 16 + s2];
    }
}

extern "C" void kernel_launch(void* const* d_in, const int* in_sizes, int n_in,
                              void* d_out, int out_size) {
    const float* in0   = (const float*)d_in[0];
    const float* g1    = (const float*)d_in[1];
    const float* be1   = (const float*)d_in[2];
    const float* w1    = (const float*)d_in[3];
    const float* b1    = (const float*)d_in[4];
    const float* w2    = (const float*)d_in[5];
    const float* b2    = (const float*)d_in[6];
    const float* wu    = (const float*)d_in[7];
    const float* bu    = (const float*)d_in[8];
    const float* g2    = (const float*)d_in[9];
    const float* be2   = (const float*)d_in[10];
    const float* wbeta = (const float*)d_in[11];
    const float* wd1   = (const float*)d_in[12];
    const float* bd1   = (const float*)d_in[13];
    const float* wd2   = (const float*)d_in[14];
    const float* bd2   = (const float*)d_in[15];
    const int*   fix   = (const int*)d_in[16];
    const int    nfix  = in_sizes[16];

    solver_kernel<<<B_SZ / 8, NTHR>>>(in0, g1, be1, w1, b1, w2, b2, wu, bu,
                                      g2, be2, wbeta, wd1, bd1, wd2, bd2,
                                      fix, nfix, (float*)d_out);
}

// round 10
// speedup vs baseline: 1.5796x; 1.1307x over previous
#include <cuda_runtime.h>
#include <cstring>

#define B_SZ   1024
#define S_SZ   2048
#define F_SZ   9
#define LB_SZ  3
#define T_STEPS 2044   // S - 1 - LB
#define LN_EPS 1e-3f
#define NTHR   512
#define POOL_BYTES 65536

extern __shared__ float pool[];   // 64 KB dynamic scratch (GEMM partials)

// ---------------------------------------------------------------------------
// Packed fp32x2 FMA (Blackwell FFMA2) — only reachable via PTX fma.rn.f32x2
// ---------------------------------------------------------------------------
__device__ __forceinline__ float2 ffma2(float2 a, float2 b, float2 c) {
    unsigned long long ra, rb, rc, rd;
    memcpy(&ra, &a, 8); memcpy(&rb, &b, 8); memcpy(&rc, &c, 8);
    asm("fma.rn.f32x2 %0, %1, %2, %3;" : "=l"(rd) : "l"(ra), "l"(rb), "l"(rc));
    float2 d; memcpy(&d, &rd, 8);
    return d;
}

// ---------------------------------------------------------------------------
// 4-col x 8-row GEMM k-slice with register weight prefetch.
// part[(n0+c)*8 + m] = sum_{k in [k0, k0+CNT)} A[k*8+m] * W[k*LD + n0+c]
// Per k-iter: 2x LDS.128 (8 rows, broadcast) + 1x LDG.128 (4 cols) + 16 FFMA2.
// ---------------------------------------------------------------------------
template<int LD, int CNT>
__device__ __forceinline__ void gemm4col(const float* __restrict__ A,
                                         const float* __restrict__ W,
                                         int n0, int k0,
                                         float* __restrict__ part)
{
    const float* Wp = W + (size_t)k0 * LD + n0;
    const float* Ap = A + k0 * 8;

    float2 acc[4][4];
#pragma unroll
    for (int c = 0; c < 4; ++c)
#pragma unroll
        for (int p = 0; p < 4; ++p) acc[c][p] = make_float2(0.f, 0.f);

    constexpr int UB = 4;
    constexpr int NB = CNT / UB;

    float4 wreg[UB];
#pragma unroll
    for (int u = 0; u < UB; ++u)
        wreg[u] = *reinterpret_cast<const float4*>(Wp + (size_t)u * LD);

#pragma unroll
    for (int kb = 0; kb < NB; ++kb) {
        float4 wnxt[UB];
        if (kb < NB - 1) {
#pragma unroll
            for (int u = 0; u < UB; ++u)
                wnxt[u] = *reinterpret_cast<const float4*>(
                    Wp + (size_t)((kb + 1) * UB + u) * LD);
        }
#pragma unroll
        for (int u = 0; u < UB; ++u) {
            const int k = kb * UB + u;
            float4 aA = *reinterpret_cast<const float4*>(Ap + k * 8);
            float4 aB = *reinterpret_cast<const float4*>(Ap + k * 8 + 4);
            float2 r0 = make_float2(aA.x, aA.y), r1 = make_float2(aA.z, aA.w);
            float2 r2 = make_float2(aB.x, aB.y), r3 = make_float2(aB.z, aB.w);
            const float wv[4] = { wreg[u].x, wreg[u].y, wreg[u].z, wreg[u].w };
#pragma unroll
            for (int c = 0; c < 4; ++c) {
                float2 w2 = make_float2(wv[c], wv[c]);
                acc[c][0] = ffma2(r0, w2, acc[c][0]);
                acc[c][1] = ffma2(r1, w2, acc[c][1]);
                acc[c][2] = ffma2(r2, w2, acc[c][2]);
                acc[c][3] = ffma2(r3, w2, acc[c][3]);
            }
        }
        if (kb < NB - 1) {
#pragma unroll
            for (int u = 0; u < UB; ++u) wreg[u] = wnxt[u];
        }
    }
    // remainder (CNT % UB, e.g. 1 for CNT=65)
#pragma unroll
    for (int k = NB * UB; k < CNT; ++k) {
        float4 w = *reinterpret_cast<const float4*>(Wp + (size_t)k * LD);
        float4 aA = *reinterpret_cast<const float4*>(Ap + k * 8);
        float4 aB = *reinterpret_cast<const float4*>(Ap + k * 8 + 4);
        float2 r0 = make_float2(aA.x, aA.y), r1 = make_float2(aA.z, aA.w);
        float2 r2 = make_float2(aB.x, aB.y), r3 = make_float2(aB.z, aB.w);
        const float wv[4] = { w.x, w.y, w.z, w.w };
#pragma unroll
        for (int c = 0; c < 4; ++c) {
            float2 w2 = make_float2(wv[c], wv[c]);
            acc[c][0] = ffma2(r0, w2, acc[c][0]);
            acc[c][1] = ffma2(r1, w2, acc[c][1]);
            acc[c][2] = ffma2(r2, w2, acc[c][2]);
            acc[c][3] = ffma2(r3, w2, acc[c][3]);
        }
    }

#pragma unroll
    for (int c = 0; c < 4; ++c)
#pragma unroll
        for (int p = 0; p < 4; ++p)
            *reinterpret_cast<float2*>(part + (n0 + c) * 8 + 2 * p) = acc[c][p];
}

// ---------------------------------------------------------------------------
// N=512 GEMM for K=33 (encoder input): 2 row-groups x 256 col-threads x 2 cols,
// register weight prefetch. Output with tanh+bias directly.
// ---------------------------------------------------------------------------
template<int K>
__device__ __forceinline__ void gemm_n512_small(const float* __restrict__ A,
                                                const float* __restrict__ W,
                                                const float* __restrict__ bias,
                                                float* __restrict__ C)
{
    const int tid = threadIdx.x;
    const int g   = tid >> 8;
    const int n0  = (tid & 255) << 1;
    const float* Wp = W + n0;
    const float b0 = bias[n0], b1 = bias[n0 + 1];
    float2 a00 = make_float2(b0, b0), a01 = make_float2(b0, b0);
    float2 a10 = make_float2(b1, b1), a11 = make_float2(b1, b1);

#pragma unroll
    for (int k = 0; k < K; ++k) {
        float2 wp = *reinterpret_cast<const float2*>(Wp + (size_t)k * 512);
        float4 av = *reinterpret_cast<const float4*>(A + k * 8 + 4 * g);
        float2 apA = make_float2(av.x, av.y), apB = make_float2(av.z, av.w);
        float2 w0 = make_float2(wp.x, wp.x), w1 = make_float2(wp.y, wp.y);
        a00 = ffma2(apA, w0, a00); a01 = ffma2(apB, w0, a01);
        a10 = ffma2(apA, w1, a10); a11 = ffma2(apB, w1, a11);
    }
    a00.x = tanhf(a00.x); a00.y = tanhf(a00.y);
    a01.x = tanhf(a01.x); a01.y = tanhf(a01.y);
    a10.x = tanhf(a10.x); a10.y = tanhf(a10.y);
    a11.x = tanhf(a11.x); a11.y = tanhf(a11.y);
    *reinterpret_cast<float2*>(C + n0 * 8 + 4 * g)           = a00;
    *reinterpret_cast<float2*>(C + n0 * 8 + 4 * g + 2)       = a01;
    *reinterpret_cast<float2*>(C + (n0 + 1) * 8 + 4 * g)     = a10;
    *reinterpret_cast<float2*>(C + (n0 + 1) * 8 + 4 * g + 2) = a11;
}

// Combine 8 partials (2048 floats each) + bias -> C. 512 threads x float4.
__device__ __forceinline__ void combine8(const float* __restrict__ bias,
                                         float* __restrict__ C)
{
    const int i = threadIdx.x;
    float4 s = reinterpret_cast<const float4*>(pool)[i];
#pragma unroll
    for (int o = 1; o < 8; ++o) {
        float4 q = reinterpret_cast<const float4*>(pool + o * 2048)[i];
        s.x += q.x; s.y += q.y; s.z += q.z; s.w += q.w;
    }
    float bv = bias[i >> 1];
    s.x += bv; s.y += bv; s.z += bv; s.w += bv;
    reinterpret_cast<float4*>(C)[i] = s;
}

// Combine 4 partials (4096 floats each) + bias + tanh -> C. 512 threads x 8 elems.
__device__ __forceinline__ void combine4_tanh(const float* __restrict__ bias,
                                              float* __restrict__ C)
{
    const int tid = threadIdx.x;
    const int i = tid * 2;                 // float4 index; elems 8*tid..8*tid+7
    float bv = bias[tid];
#pragma unroll
    for (int h = 0; h < 2; ++h) {
        float4 s = reinterpret_cast<const float4*>(pool)[i + h];
#pragma unroll
        for (int o = 1; o < 4; ++o) {
            float4 q = reinterpret_cast<const float4*>(pool + o * 4096)[i + h];
            s.x += q.x; s.y += q.y; s.z += q.z; s.w += q.w;
        }
        s.x = tanhf(s.x + bv); s.y = tanhf(s.y + bv);
        s.z = tanhf(s.z + bv); s.w = tanhf(s.w + bv);
        reinterpret_cast<float4*>(C)[i + h] = s;
    }
}

// ---------------------------------------------------------------------------
// Persistent kernel: 128 CTAs x 8 batch rows x 512 threads.
// ---------------------------------------------------------------------------
__global__ __launch_bounds__(NTHR)
void solver_kernel(const float* __restrict__ in0,
                   const float* __restrict__ g1,  const float* __restrict__ be1,
                   const float* __restrict__ w1,  const float* __restrict__ b1,
                   const float* __restrict__ w2,  const float* __restrict__ b2,
                   const float* __restrict__ wu,  const float* __restrict__ bu,
                   const float* __restrict__ g2,  const float* __restrict__ be2,
                   const float* __restrict__ wbeta,
                   const float* __restrict__ wd1, const float* __restrict__ bd1,
                   const float* __restrict__ wd2, const float* __restrict__ bd2,
                   const int*   __restrict__ fix, int nfix,
                   float* __restrict__ out)
{
    __shared__ __align__(16) float x33[33 * 8];      // LN'd encoder input
    __shared__ __align__(16) float buf512[512 * 8];  // h1 / t
    __shared__ __align__(16) float hbuf[256 * 8];    // h / dec2 partials
    __shared__ __align__(16) float ubuf[256 * 8];    // u
    __shared__ __align__(16) float comb[257 * 8];    // [LN2(u), ect]
    __shared__ __align__(16) float win[3 * 8 * 8];   // window ring [phys][n][m]
    __shared__ __align__(16) float ybuf[8 * 8 * 16]; // 16-step output staging

    const int tid  = threadIdx.x;
    const int wid  = tid >> 5, lane = tid & 31;
    const int b_base = blockIdx.x * 8;

    const int f0 = (nfix > 0) ? fix[0] : -1;
    const int f1 = (nfix > 1) ? fix[1] : -1;

    // init window = inputs[:, 0:3, 1:9]
    for (int idx = tid; idx < 192; idx += NTHR) {
        int j = idx / 64, rem = idx % 64, n = rem >> 3, m = rem & 7;
        win[j * 64 + n * 8 + m] = in0[((size_t)(b_base + m) * S_SZ + j) * F_SZ + 1 + n];
    }
    __syncthreads();

    for (int step = 0; step < T_STEPS; ++step) {
        const int i = step + LB_SZ;
        const int r = step % 3;

        // ---- LN1: gamma/beta broadcast over LAST axis (index = lane) ----
        if (wid < 8) {
            const int m = wid;
            for (int j = 0; j < 3; ++j) {
                int t = i - 3 + j;
                float v = 0.f;
                if (lane < 11) {
                    if (lane < 3) {
                        size_t base = ((size_t)(b_base + m) * S_SZ + t) * F_SZ;
                        float L = in0[base];
                        if (lane < 2) v = L;                      // loading, cumsum
                        else v = (t > 0) ? (L - in0[base - F_SZ]) : 0.f;
                    } else {
                        v = win[((r + j) % 3) * 64 + (lane - 3) * 8 + m];
                    }
                }
                float s = v, s2 = v * v;
#pragma unroll
                for (int off = 16; off > 0; off >>= 1) {
                    s  += __shfl_xor_sync(0xffffffffu, s,  off);
                    s2 += __shfl_xor_sync(0xffffffffu, s2, off);
                }
                float mean = s * (1.f / 11.f);
                float var  = s2 * (1.f / 11.f) - mean * mean;
                float rs   = rsqrtf(var + LN_EPS);
                if (lane < 11)
                    x33[(j * 11 + lane) * 8 + m] = (v - mean) * rs * g1[lane] + be1[lane];
            }
        }
        __syncthreads();

        gemm_n512_small<33>(x33, w1, b1, buf512);          // h1 = tanh(x@w1+b1)
        __syncthreads();

        // ---- enc2: h = h1@w2 + b2, N=256 K=512, 8-way k-split x 4 cols ----
        {
            const int oct = tid >> 6, n0 = (tid & 63) << 2;
            gemm4col<256, 64>(buf512, w2, n0, oct * 64, pool + oct * 2048);
        }
        __syncthreads();
        combine8(b2, hbuf);
        __syncthreads();

        // ---- upd: u = h@wu + bu, N=256 K=256, 8-way k-split x 4 cols ----
        {
            const int oct = tid >> 6, n0 = (tid & 63) << 2;
            gemm4col<256, 32>(hbuf, wu, n0, oct * 32, pool + oct * 2048);
        }
        __syncthreads();
        combine8(bu, ubuf);
        __syncthreads();

        // ---- LN2(u) + ect = h@beta_w -> comb[257][8] ----
        if (wid < 8) {
            const int m = wid;
            float uv[8];
            float su = 0.f, sq = 0.f, se = 0.f;
#pragma unroll
            for (int q = 0; q < 8; ++q) {
                int n = lane + 32 * q;
                float x = ubuf[n * 8 + m];
                uv[q] = x; su += x; sq += x * x;
                se += hbuf[n * 8 + m] * wbeta[n];
            }
#pragma unroll
            for (int off = 16; off > 0; off >>= 1) {
                su += __shfl_xor_sync(0xffffffffu, su, off);
                sq += __shfl_xor_sync(0xffffffffu, sq, off);
                se += __shfl_xor_sync(0xffffffffu, se, off);
            }
            float mean = su * (1.f / 256.f);
            float var  = sq * (1.f / 256.f) - mean * mean;
            float rs   = rsqrtf(var + LN_EPS);
#pragma unroll
            for (int q = 0; q < 8; ++q) {
                int n = lane + 32 * q;
                comb[n * 8 + m] = (uv[q] - mean) * rs * g2[n] + be2[n];
            }
            if (lane == 0) comb[256 * 8 + m] = se;
        }
        __syncthreads();

        // ---- dec1: t = tanh(comb@wd1 + bd1), N=512 K=257, 4-way split x 4 cols ----
        {
            const int q = tid >> 7, n0 = (tid & 127) << 2;
            if (q == 0)
                gemm4col<512, 65>(comb, wd1, n0, 0, pool);
            else
                gemm4col<512, 64>(comb, wd1, n0, q * 64 + 1, pool + q * 4096);
        }
        __syncthreads();
        combine4_tanh(bd1, buf512);
        __syncthreads();

        // ---- dec2: y = t@wd2 + bd2, 8-way k-split, partials in hbuf ----
        {
            const int ks = tid >> 6, nm = tid & 63;
            const int n = nm & 7, m = nm >> 3, k0 = ks * 64;
            float a0 = 0.f, a1 = 0.f;
#pragma unroll 8
            for (int k = 0; k < 64; k += 2) {
                a0 += buf512[(k0 + k)     * 8 + m] * wd2[(k0 + k)     * 8 + n];
                a1 += buf512[(k0 + k + 1) * 8 + m] * wd2[(k0 + k + 1) * 8 + n];
            }
            hbuf[ks * 64 + nm] = a0 + a1;
        }
        __syncthreads();
        if (tid < 64) {
            const int n = tid & 7, m = tid >> 3;
            float acc = bd2[n];
#pragma unroll
            for (int ks = 0; ks < 8; ++ks) acc += hbuf[ks * 64 + tid];
            if (n == f0 || n == f1)
                acc = in0[((size_t)(b_base + m) * S_SZ + (i + 1)) * F_SZ + 1 + n];
            ybuf[(n * 8 + m) * 16 + (step & 15)] = acc;
            win[r * 64 + n * 8 + m] = acc;
        }
        __syncthreads();

        if ((step & 15) == 15 && tid < 64) {
            const int n = tid >> 3, m = tid & 7;
            const float4* src = reinterpret_cast<const float4*>(&ybuf[(n * 8 + m) * 16]);
            float4* dst = reinterpret_cast<float4*>(
                &out[(size_t)n * B_SZ * T_STEPS + (size_t)(b_base + m) * T_STEPS + (step - 15)]);
            dst[0] = src[0]; dst[1] = src[1]; dst[2] = src[2]; dst[3] = src[3];
        }
    }

    // tail flush (T_STEPS % 16 == 12)
    if (tid < 64) {
        const int n = tid >> 3, m = tid & 7;
        const int step0 = (T_STEPS / 16) * 16;
        for (int s2 = 0; s2 < T_STEPS - step0; ++s2)
            out[(size_t)n * B_SZ * T_STEPS + (size_t)(b_base + m) * T_STEPS + step0 + s2]
                = ybuf[(n * 8 + m) * 16 + s2];
    }
}

extern "C" void kernel_launch(void* const* d_in, const int* in_sizes, int n_in,
                              void* d_out, int out_size) {
    const float* in0   = (const float*)d_in[0];
    const float* g1    = (const float*)d_in[1];
    const float* be1   = (const float*)d_in[2];
    const float* w1    = (const float*)d_in[3];
    const float* b1    = (const float*)d_in[4];
    const float* w2    = (const float*)d_in[5];
    const float* b2    = (const float*)d_in[6];
    const float* wu    = (const float*)d_in[7];
    const float* bu    = (const float*)d_in[8];
    const float* g2    = (const float*)d_in[9];
    const float* be2   = (const float*)d_in[10];
    const float* wbeta = (const float*)d_in[11];
    const float* wd1   = (const float*)d_in[12];
    const float* bd1   = (const float*)d_in[13];
    const float* wd2   = (const float*)d_in[14];
    const float* bd2   = (const float*)d_in[15];
    const int*   fix   = (const int*)d_in[16];
    const int    nfix  = in_sizes[16];

    cudaFuncSetAttribute(solver_kernel,
                         cudaFuncAttributeMaxDynamicSharedMemorySize, POOL_BYTES);

    solver_kernel<<<B_SZ / 8, NTHR, POOL_BYTES>>>(
        in0, g1, be1, w1, b1, w2, b2, wu, bu,
        g2, be2, wbeta, wd1, bd1, wd2, bd2,
        fix, nfix, (float*)d_out);
}

// round 11
// speedup vs baseline: 1.8360x; 1.1623x over previous
#include <cuda_runtime.h>
#include <cstring>

#define B_SZ   1024
#define S_SZ   2048
#define F_SZ   9
#define LB_SZ  3
#define T_STEPS 2044   // S - 1 - LB
#define LN_EPS 1e-3f
#define NTHR   512

// Partial pools: col-groups of 8 cols padded to 68 floats (64 data + 4 pad)
// so partial STS.128 lane-stride is 68 words (4 mod 32) -> conflict-free.
#define P16 2176                 // 32 groups * 68  (N=256 GEMMs, 16 slices)
#define P8  4352                 // 64 groups * 68  (N=512 dec1, 8 slices)
#define POOL_FLOATS 34816        // max(16*P16, 8*P8)
#define POOL_BYTES  (POOL_FLOATS * 4)

extern __shared__ float pool[];  // 136 KB dynamic scratch (GEMM partials)

// ---------------------------------------------------------------------------
// Packed fp32x2 FMA (Blackwell FFMA2) — only reachable via PTX fma.rn.f32x2
// ---------------------------------------------------------------------------
__device__ __forceinline__ float2 ffma2(float2 a, float2 b, float2 c) {
    unsigned long long ra, rb, rc, rd;
    memcpy(&ra, &a, 8); memcpy(&rb, &b, 8); memcpy(&rc, &c, 8);
    asm("fma.rn.f32x2 %0, %1, %2, %3;" : "=l"(rd) : "l"(ra), "l"(rb), "l"(rc));
    float2 d; memcpy(&d, &rd, 8);
    return d;
}

// ---------------------------------------------------------------------------
// 8-col x 8-row GEMM k-slice, register weight prefetch (UB=2, dynamic outer
// loop so ptxas keeps the pipeline live — do NOT fully unroll kb).
// partBase[colg*68 + c*8 + m] = sum_{k in [k0,k0+CNT)} A[k*8+m]*W[k*LD+colg*8+c]
// Per k-iter: 2x LDS.128 (8 rows, broadcast) + 2x LDG.128 (8 cols) + 32 FFMA2.
// ---------------------------------------------------------------------------
template<int LD, int CNT>
__device__ __forceinline__ void gemm8col(const float* __restrict__ A,
                                         const float* __restrict__ W,
                                         int colg, int k0,
                                         float* __restrict__ partBase)
{
    const float* Wp = W + (size_t)k0 * LD + colg * 8;
    const float* Ap = A + k0 * 8;

    float2 acc[8][4];
#pragma unroll
    for (int c = 0; c < 8; ++c)
#pragma unroll
        for (int p = 0; p < 4; ++p) acc[c][p] = make_float2(0.f, 0.f);

    constexpr int UB = 2;
    constexpr int NB = CNT / UB;

    float4 wlo[UB], whi[UB];
#pragma unroll
    for (int u = 0; u < UB; ++u) {
        wlo[u] = *reinterpret_cast<const float4*>(Wp + (size_t)u * LD);
        whi[u] = *reinterpret_cast<const float4*>(Wp + (size_t)u * LD + 4);
    }

#pragma unroll 1
    for (int kb = 0; kb < NB - 1; ++kb) {
        float4 nlo[UB], nhi[UB];
        const float* Wn = Wp + (size_t)(kb + 1) * UB * LD;
#pragma unroll
        for (int u = 0; u < UB; ++u) {
            nlo[u] = *reinterpret_cast<const float4*>(Wn + (size_t)u * LD);
            nhi[u] = *reinterpret_cast<const float4*>(Wn + (size_t)u * LD + 4);
        }
#pragma unroll
        for (int u = 0; u < UB; ++u) {
            const int k = kb * UB + u;
            float4 aA = *reinterpret_cast<const float4*>(Ap + k * 8);
            float4 aB = *reinterpret_cast<const float4*>(Ap + k * 8 + 4);
            float2 r0 = make_float2(aA.x, aA.y), r1 = make_float2(aA.z, aA.w);
            float2 r2 = make_float2(aB.x, aB.y), r3 = make_float2(aB.z, aB.w);
            const float wv[8] = { wlo[u].x, wlo[u].y, wlo[u].z, wlo[u].w,
                                  whi[u].x, whi[u].y, whi[u].z, whi[u].w };
#pragma unroll
            for (int c = 0; c < 8; ++c) {
                float2 w2 = make_float2(wv[c], wv[c]);
                acc[c][0] = ffma2(r0, w2, acc[c][0]);
                acc[c][1] = ffma2(r1, w2, acc[c][1]);
                acc[c][2] = ffma2(r2, w2, acc[c][2]);
                acc[c][3] = ffma2(r3, w2, acc[c][3]);
            }
        }
#pragma unroll
        for (int u = 0; u < UB; ++u) { wlo[u] = nlo[u]; whi[u] = nhi[u]; }
    }
    // last full batch (consume final prefetch)
#pragma unroll
    for (int u = 0; u < UB; ++u) {
        const int k = (NB - 1) * UB + u;
        float4 aA = *reinterpret_cast<const float4*>(Ap + k * 8);
        float4 aB = *reinterpret_cast<const float4*>(Ap + k * 8 + 4);
        float2 r0 = make_float2(aA.x, aA.y), r1 = make_float2(aA.z, aA.w);
        float2 r2 = make_float2(aB.x, aB.y), r3 = make_float2(aB.z, aB.w);
        const float wv[8] = { wlo[u].x, wlo[u].y, wlo[u].z, wlo[u].w,
                              whi[u].x, whi[u].y, whi[u].z, whi[u].w };
#pragma unroll
        for (int c = 0; c < 8; ++c) {
            float2 w2 = make_float2(wv[c], wv[c]);
            acc[c][0] = ffma2(r0, w2, acc[c][0]);
            acc[c][1] = ffma2(r1, w2, acc[c][1]);
            acc[c][2] = ffma2(r2, w2, acc[c][2]);
            acc[c][3] = ffma2(r3, w2, acc[c][3]);
        }
    }
    // remainder (CNT % UB, e.g. 1 for CNT=33)
#pragma unroll
    for (int k = NB * UB; k < CNT; ++k) {
        float4 wl = *reinterpret_cast<const float4*>(Wp + (size_t)k * LD);
        float4 wh = *reinterpret_cast<const float4*>(Wp + (size_t)k * LD + 4);
        float4 aA = *reinterpret_cast<const float4*>(Ap + k * 8);
        float4 aB = *reinterpret_cast<const float4*>(Ap + k * 8 + 4);
        float2 r0 = make_float2(aA.x, aA.y), r1 = make_float2(aA.z, aA.w);
        float2 r2 = make_float2(aB.x, aB.y), r3 = make_float2(aB.z, aB.w);
        const float wv[8] = { wl.x, wl.y, wl.z, wl.w, wh.x, wh.y, wh.z, wh.w };
#pragma unroll
        for (int c = 0; c < 8; ++c) {
            float2 w2 = make_float2(wv[c], wv[c]);
            acc[c][0] = ffma2(r0, w2, acc[c][0]);
            acc[c][1] = ffma2(r1, w2, acc[c][1]);
            acc[c][2] = ffma2(r2, w2, acc[c][2]);
            acc[c][3] = ffma2(r3, w2, acc[c][3]);
        }
    }

    float* pp = partBase + colg * 68;
#pragma unroll
    for (int c = 0; c < 8; ++c) {
        *reinterpret_cast<float4*>(pp + c * 8) =
            make_float4(acc[c][0].x, acc[c][0].y, acc[c][1].x, acc[c][1].y);
        *reinterpret_cast<float4*>(pp + c * 8 + 4) =
            make_float4(acc[c][2].x, acc[c][2].y, acc[c][3].x, acc[c][3].y);
    }
}

// Combine 16 padded partials (stride P16) + bias -> C[2048]. 512 thr x float4.
__device__ __forceinline__ void combine16(const float* __restrict__ bias,
                                          float* __restrict__ C)
{
    const int i = threadIdx.x;
    const int base = (i >> 4) * 68 + (i & 15) * 4;
    float4 s = *reinterpret_cast<const float4*>(pool + base);
#pragma unroll
    for (int o = 1; o < 16; ++o) {
        float4 q = *reinterpret_cast<const float4*>(pool + o * P16 + base);
        s.x += q.x; s.y += q.y; s.z += q.z; s.w += q.w;
    }
    float bv = bias[i >> 1];
    s.x += bv; s.y += bv; s.z += bv; s.w += bv;
    *reinterpret_cast<float4*>(C + i * 4) = s;
}

// Combine 8 padded partials (stride P8) + bias + tanh -> C[4096]. 8 elem/thr.
__device__ __forceinline__ void combine8_tanh(const float* __restrict__ bias,
                                              float* __restrict__ C)
{
    const int tid = threadIdx.x;
    const int base = (tid >> 3) * 68 + (tid & 7) * 8;
    float bv = bias[tid];
    float4 s0 = *reinterpret_cast<const float4*>(pool + base);
    float4 s1 = *reinterpret_cast<const float4*>(pool + base + 4);
#pragma unroll
    for (int o = 1; o < 8; ++o) {
        float4 q0 = *reinterpret_cast<const float4*>(pool + o * P8 + base);
        float4 q1 = *reinterpret_cast<const float4*>(pool + o * P8 + base + 4);
        s0.x += q0.x; s0.y += q0.y; s0.z += q0.z; s0.w += q0.w;
        s1.x += q1.x; s1.y += q1.y; s1.z += q1.z; s1.w += q1.w;
    }
    s0.x = tanhf(s0.x + bv); s0.y = tanhf(s0.y + bv);
    s0.z = tanhf(s0.z + bv); s0.w = tanhf(s0.w + bv);
    s1.x = tanhf(s1.x + bv); s1.y = tanhf(s1.y + bv);
    s1.z = tanhf(s1.z + bv); s1.w = tanhf(s1.w + bv);
    *reinterpret_cast<float4*>(C + tid * 8)     = s0;
    *reinterpret_cast<float4*>(C + tid * 8 + 4) = s1;
}

// ---------------------------------------------------------------------------
// N=512 GEMM for K=33 (encoder input): 2 row-groups x 256 col-threads x 2 cols.
// K tiny, weights L2-hot; tanh+bias fused on output.
// ---------------------------------------------------------------------------
template<int K>
__device__ __forceinline__ void gemm_n512_small(const float* __restrict__ A,
                                                const float* __restrict__ W,
                                                const float* __restrict__ bias,
                                                float* __restrict__ C)
{
    const int tid = threadIdx.x;
    const int g   = tid >> 8;
    const int n0  = (tid & 255) << 1;
    const float* Wp = W + n0;
    const float b0 = bias[n0], b1 = bias[n0 + 1];
    float2 a00 = make_float2(b0, b0), a01 = make_float2(b0, b0);
    float2 a10 = make_float2(b1, b1), a11 = make_float2(b1, b1);

#pragma unroll
    for (int k = 0; k < K; ++k) {
        float2 wp = *reinterpret_cast<const float2*>(Wp + (size_t)k * 512);
        float4 av = *reinterpret_cast<const float4*>(A + k * 8 + 4 * g);
        float2 apA = make_float2(av.x, av.y), apB = make_float2(av.z, av.w);
        float2 w0 = make_float2(wp.x, wp.x), w1 = make_float2(wp.y, wp.y);
        a00 = ffma2(apA, w0, a00); a01 = ffma2(apB, w0, a01);
        a10 = ffma2(apA, w1, a10); a11 = ffma2(apB, w1, a11);
    }
    a00.x = tanhf(a00.x); a00.y = tanhf(a00.y);
    a01.x = tanhf(a01.x); a01.y = tanhf(a01.y);
    a10.x = tanhf(a10.x); a10.y = tanhf(a10.y);
    a11.x = tanhf(a11.x); a11.y = tanhf(a11.y);
    *reinterpret_cast<float2*>(C + n0 * 8 + 4 * g)           = a00;
    *reinterpret_cast<float2*>(C + n0 * 8 + 4 * g + 2)       = a01;
    *reinterpret_cast<float2*>(C + (n0 + 1) * 8 + 4 * g)     = a10;
    *reinterpret_cast<float2*>(C + (n0 + 1) * 8 + 4 * g + 2) = a11;
}

// ---------------------------------------------------------------------------
// Persistent kernel: 128 CTAs x 8 batch rows x 512 threads.
// ---------------------------------------------------------------------------
__global__ __launch_bounds__(NTHR)
void solver_kernel(const float* __restrict__ in0,
                   const float* __restrict__ g1,  const float* __restrict__ be1,
                   const float* __restrict__ w1,  const float* __restrict__ b1,
                   const float* __restrict__ w2,  const float* __restrict__ b2,
                   const float* __restrict__ wu,  const float* __restrict__ bu,
                   const float* __restrict__ g2,  const float* __restrict__ be2,
                   const float* __restrict__ wbeta,
                   const float* __restrict__ wd1, const float* __restrict__ bd1,
                   const float* __restrict__ wd2, const float* __restrict__ bd2,
                   const int*   __restrict__ fix, int nfix,
                   float* __restrict__ out)
{
    __shared__ __align__(16) float x33[33 * 8];      // LN'd encoder input
    __shared__ __align__(16) float buf512[512 * 8];  // h1 / t
    __shared__ __align__(16) float hbuf[256 * 8];    // h / dec2 partials
    __shared__ __align__(16) float ubuf[256 * 8];    // u
    __shared__ __align__(16) float comb[257 * 8];    // [LN2(u), ect]
    __shared__ __align__(16) float win[3 * 8 * 8];   // window ring [phys][n][m]
    __shared__ __align__(16) float ybuf[8 * 8 * 16]; // 16-step output staging

    const int tid  = threadIdx.x;
    const int wid  = tid >> 5, lane = tid & 31;
    const int b_base = blockIdx.x * 8;

    const int f0 = (nfix > 0) ? fix[0] : -1;
    const int f1 = (nfix > 1) ? fix[1] : -1;

    // init window = inputs[:, 0:3, 1:9]
    for (int idx = tid; idx < 192; idx += NTHR) {
        int j = idx / 64, rem = idx % 64, n = rem >> 3, m = rem & 7;
        win[j * 64 + n * 8 + m] = in0[((size_t)(b_base + m) * S_SZ + j) * F_SZ + 1 + n];
    }
    __syncthreads();

    for (int step = 0; step < T_STEPS; ++step) {
        const int i = step + LB_SZ;
        const int r = step % 3;

        // ---- LN1: gamma/beta broadcast over LAST axis (index = lane) ----
        if (wid < 8) {
            const int m = wid;
            for (int j = 0; j < 3; ++j) {
                int t = i - 3 + j;
                float v = 0.f;
                if (lane < 11) {
                    if (lane < 3) {
                        size_t base = ((size_t)(b_base + m) * S_SZ + t) * F_SZ;
                        float L = in0[base];
                        if (lane < 2) v = L;                      // loading, cumsum
                        else v = (t > 0) ? (L - in0[base - F_SZ]) : 0.f;
                    } else {
                        v = win[((r + j) % 3) * 64 + (lane - 3) * 8 + m];
                    }
                }
                float s = v, s2 = v * v;
#pragma unroll
                for (int off = 16; off > 0; off >>= 1) {
                    s  += __shfl_xor_sync(0xffffffffu, s,  off);
                    s2 += __shfl_xor_sync(0xffffffffu, s2, off);
                }
                float mean = s * (1.f / 11.f);
                float var  = s2 * (1.f / 11.f) - mean * mean;
                float rs   = rsqrtf(var + LN_EPS);
                if (lane < 11)
                    x33[(j * 11 + lane) * 8 + m] = (v - mean) * rs * g1[lane] + be1[lane];
            }
        }
        __syncthreads();

        gemm_n512_small<33>(x33, w1, b1, buf512);          // h1 = tanh(x@w1+b1)
        __syncthreads();

        // ---- enc2: h = h1@w2 + b2, N=256 K=512, 16-way k-split x 8 cols ----
        {
            const int slice = tid >> 5, colg = tid & 31;
            gemm8col<256, 32>(buf512, w2, colg, slice * 32, pool + slice * P16);
        }
        __syncthreads();
        combine16(b2, hbuf);
        __syncthreads();

        // ---- upd: u = h@wu + bu, N=256 K=256, 16-way k-split x 8 cols ----
        {
            const int slice = tid >> 5, colg = tid & 31;
            gemm8col<256, 16>(hbuf, wu, colg, slice * 16, pool + slice * P16);
        }
        __syncthreads();
        combine16(bu, ubuf);
        __syncthreads();

        // ---- LN2(u) + ect = h@beta_w -> comb[257][8] ----
        if (wid < 8) {
            const int m = wid;
            float uv[8];
            float su = 0.f, sq = 0.f, se = 0.f;
#pragma unroll
            for (int q = 0; q < 8; ++q) {
                int n = lane + 32 * q;
                float x = ubuf[n * 8 + m];
                uv[q] = x; su += x; sq += x * x;
                se += hbuf[n * 8 + m] * wbeta[n];
            }
#pragma unroll
            for (int off = 16; off > 0; off >>= 1) {
                su += __shfl_xor_sync(0xffffffffu, su, off);
                sq += __shfl_xor_sync(0xffffffffu, sq, off);
                se += __shfl_xor_sync(0xffffffffu, se, off);
            }
            float mean = su * (1.f / 256.f);
            float var  = sq * (1.f / 256.f) - mean * mean;
            float rs   = rsqrtf(var + LN_EPS);
#pragma unroll
            for (int q = 0; q < 8; ++q) {
                int n = lane + 32 * q;
                comb[n * 8 + m] = (uv[q] - mean) * rs * g2[n] + be2[n];
            }
            if (lane == 0) comb[256 * 8 + m] = se;
        }
        __syncthreads();

        // ---- dec1: t = tanh(comb@wd1 + bd1), N=512 K=257, 8-way split x 8 cols ----
        {
            const int slice = tid >> 6, colg = tid & 63;
            if (slice == 0)
                gemm8col<512, 33>(comb, wd1, colg, 0, pool);
            else
                gemm8col<512, 32>(comb, wd1, colg, slice * 32 + 1, pool + slice * P8);
        }
        __syncthreads();
        combine8_tanh(bd1, buf512);
        __syncthreads();

        // ---- dec2: y = t@wd2 + bd2, 8-way k-split, partials in hbuf ----
        {
            const int ks = tid >> 6, nm = tid & 63;
            const int n = nm & 7, m = nm >> 3, k0 = ks * 64;
            float a0 = 0.f, a1 = 0.f;
#pragma unroll 8
            for (int k = 0; k < 64; k += 2) {
                a0 += buf512[(k0 + k)     * 8 + m] * wd2[(k0 + k)     * 8 + n];
                a1 += buf512[(k0 + k + 1) * 8 + m] * wd2[(k0 + k + 1) * 8 + n];
            }
            hbuf[ks * 64 + nm] = a0 + a1;
        }
        __syncthreads();
        if (tid < 64) {
            const int n = tid & 7, m = tid >> 3;
            float acc = bd2[n];
#pragma unroll
            for (int ks = 0; ks < 8; ++ks) acc += hbuf[ks * 64 + tid];
            if (n == f0 || n == f1)
                acc = in0[((size_t)(b_base + m) * S_SZ + (i + 1)) * F_SZ + 1 + n];
            ybuf[(n * 8 + m) * 16 + (step & 15)] = acc;
            win[r * 64 + n * 8 + m] = acc;
        }
        __syncthreads();

        if ((step & 15) == 15 && tid < 64) {
            const int n = tid >> 3, m = tid & 7;
            const float4* src = reinterpret_cast<const float4*>(&ybuf[(n * 8 + m) * 16]);
            float4* dst = reinterpret_cast<float4*>(
                &out[(size_t)n * B_SZ * T_STEPS + (size_t)(b_base + m) * T_STEPS + (step - 15)]);
            dst[0] = src[0]; dst[1] = src[1]; dst[2] = src[2]; dst[3] = src[3];
        }
    }

    // tail flush (T_STEPS % 16 == 12)
    if (tid < 64) {
        const int n = tid >> 3, m = tid & 7;
        const int step0 = (T_STEPS / 16) * 16;
        for (int s2 = 0; s2 < T_STEPS - step0; ++s2)
            out[(size_t)n * B_SZ * T_STEPS + (size_t)(b_base + m) * T_STEPS + step0 + s2]
                = ybuf[(n * 8 + m) * 16 + s2];
    }
}

extern "C" void kernel_launch(void* const* d_in, const int* in_sizes, int n_in,
                              void* d_out, int out_size) {
    const float* in0   = (const float*)d_in[0];
    const float* g1    = (const float*)d_in[1];
    const float* be1   = (const float*)d_in[2];
    const float* w1    = (const float*)d_in[3];
    const float* b1    = (const float*)d_in[4];
    const float* w2    = (const float*)d_in[5];
    const float* b2    = (const float*)d_in[6];
    const float* wu    = (const float*)d_in[7];
    const float* bu    = (const float*)d_in[8];
    const float* g2    = (const float*)d_in[9];
    const float* be2   = (const float*)d_in[10];
    const float* wbeta = (const float*)d_in[11];
    const float* wd1   = (const float*)d_in[12];
    const float* bd1   = (const float*)d_in[13];
    const float* wd2   = (const float*)d_in[14];
    const float* bd2   = (const float*)d_in[15];
    const int*   fix   = (const int*)d_in[16];
    const int    nfix  = in_sizes[16];

    cudaFuncSetAttribute(solver_kernel,
                         cudaFuncAttributeMaxDynamicSharedMemorySize, POOL_BYTES);

    solver_kernel<<<B_SZ / 8, NTHR, POOL_BYTES>>>(
        in0, g1, be1, w1, b1, w2, b2, wu, bu,
        g2, be2, wbeta, wd1, bd1, wd2, bd2,
        fix, nfix, (float*)d_out);
}